// round 5
// baseline (speedup 1.0000x reference)
#include <cuda_runtime.h>

// Problem shape (fixed by the dataset): B=8, N=1024, C=128, H=W=512.
static constexpr int  Nc = 1024;
static constexpr int  C4 = 32;            // 128 floats = 32 float4 per pixel
static constexpr int  HW_SHIFT = 18;      // H*W = 2^18 pixels per batch image
static constexpr long long PIX = 8LL << HW_SHIFT;   // 2,097,152 pixels
static constexpr int  P = 4;              // pixels per strip (measured MLP sweet spot)
static constexpr int  S = 4;              // strips per warp (software pipeline depth)

// Each warp owns S*P = 16 consecutive pixels, processed as S strips of P.
// Pipeline: indices for strip i+1 are prefetched while strip i's gathers and
// stores are in flight, so the ~600cyc DRAM index latency is paid once per
// warp instead of once per strip.
//  - index load: lanes 0..3 load 4 int32 (one sector), shfl-broadcast
//  - gather: 4 INDEPENDENT LDG.128 per thread (MLP=4), feat rows L1/L2-resident
//  - store: 4 coalesced 512B STG.128 bursts, streaming (__stcs), write-once
__global__ void __launch_bounds__(256)
convert2image_pipe(const float4* __restrict__ feat,   // [B, N, C/4]
                   const int*    __restrict__ slic,   // [B*H*W]
                   float4*       __restrict__ out)    // [B*H*W, C/4]
{
    const long long warp_gid = (long long)blockIdx.x * (blockDim.x >> 5)
                             + (threadIdx.x >> 5);
    const long long pix_base = warp_gid * (long long)(P * S);
    const int lane = threadIdx.x & 31;

    // All S*P pixels of a warp lie in one batch image (16 divides 2^18).
    const int b = (int)(pix_base >> HW_SHIFT);
    const float4* __restrict__ fb = feat + ((long long)b * Nc) * C4;
    float4* __restrict__ o = out + (pix_base << 5) + lane;

    // Prologue: indices for strip 0.
    int myidx = 0;
    if (lane < P) myidx = __ldg(slic + pix_base + lane) - 1;   // 1-indexed labels

    #pragma unroll
    for (int s = 0; s < S; s++) {
        // Issue this strip's 4 independent gathers.
        float4 v[P];
        #pragma unroll
        for (int p = 0; p < P; p++) {
            const int idx = __shfl_sync(0xffffffffu, myidx, p);
            v[p] = make_float4(0.f, 0.f, 0.f, 0.f);
            if ((unsigned)idx < (unsigned)Nc) {
                v[p] = __ldg(fb + (long long)idx * C4 + lane);   // MLP=P
            }
        }

        // Prefetch next strip's indices while gathers/stores drain.
        if (s + 1 < S) {
            if (lane < P)
                myidx = __ldg(slic + pix_base + (long long)(s + 1) * P + lane) - 1;
        }

        // Streaming stores: write-once, evict-first keeps feat cache-resident.
        float4* os = o + ((long long)s * P << 5);
        #pragma unroll
        for (int p = 0; p < P; p++) {
            __stcs(os + (p << 5), v[p]);
        }
    }
}

extern "C" void kernel_launch(void* const* d_in, const int* in_sizes, int n_in,
                              void* d_out, int out_size)
{
    const float4* feat = (const float4*)d_in[0];   // graph_lstm_output fp32 [B,N,C]
    const int*    slic = (const int*)d_in[1];      // slic_output int32 [B,H,W,1]
    float4*       out  = (float4*)d_out;           // fp32 [B,H,W,C]

    const int threads = 256;                                  // 8 warps
    const long long pixels_per_block = (threads / 32) * (long long)(P * S); // 128
    const unsigned blocks = (unsigned)(PIX / pixels_per_block);             // 16,384 exact

    convert2image_pipe<<<blocks, threads>>>(feat, slic, out);
}

// round 6
// speedup vs baseline: 1.0152x; 1.0152x over previous
#include <cuda_runtime.h>

// Problem shape (fixed by the dataset): B=8, N=1024, C=128, H=W=512.
static constexpr int  Nc = 1024;
static constexpr int  C4 = 32;            // 128 floats = 32 float4 per pixel
static constexpr int  HW_SHIFT = 18;      // H*W = 2^18 pixels per batch image
static constexpr long long PIX = 8LL << HW_SHIFT;   // 2,097,152 pixels
static constexpr int  P = 4;              // pixels per warp (measured MLP sweet spot)

// Measured-optimal configuration (R2): one warp per 4 consecutive pixels,
// lane l owns float4-chunk l of each pixel's 128-float feature row.
//  - index load: lanes 0..3 load 4 consecutive int32 (one sector), shfl-bcast
//  - gather: 4 INDEPENDENT LDG.128 per thread (MLP=4), feat rows L1/L2-resident
//  - store: 4 coalesced 512B STG.128 bursts, streaming (__stcs): output is
//    write-once, evict-first keeps the 4MB feature table cache-resident.
// Many small warps (grid=65536) beat coarser variants: CTA-level parallelism
// fills the L1tex wavefront queues evenly across all 148 SMs; every
// granularity-coarsening variant (P=8, 512-thr blocks, S=4 pipeline) measured
// 1-4us slower. 141.8us = 7.65TB/s effective vs 134us compulsory-traffic floor.
__global__ void __launch_bounds__(256)
convert2image_gather4(const float4* __restrict__ feat,   // [B, N, C/4]
                      const int*    __restrict__ slic,   // [B*H*W]
                      float4*       __restrict__ out)    // [B*H*W, C/4]
{
    const long long warp_gid = (long long)blockIdx.x * (blockDim.x >> 5)
                             + (threadIdx.x >> 5);
    const long long pix0 = warp_gid * P;
    const int lane = threadIdx.x & 31;

    if (pix0 >= PIX) return;

    // All P pixels of a warp lie in the same batch image (P divides H*W).
    const int b = (int)(pix0 >> HW_SHIFT);
    const float4* __restrict__ fb = feat + ((long long)b * Nc) * C4;

    // Lanes 0..P-1 fetch the P segment labels (one 16B sector total).
    int myidx = 0;
    if (lane < P) myidx = __ldg(slic + pix0 + lane) - 1;   // labels 1-indexed

    float4 v[P];
    #pragma unroll
    for (int p = 0; p < P; p++) {
        const int idx = __shfl_sync(0xffffffffu, myidx, p);
        v[p] = make_float4(0.f, 0.f, 0.f, 0.f);
        if ((unsigned)idx < (unsigned)Nc) {
            v[p] = __ldg(fb + (long long)idx * C4 + lane);  // independent -> MLP=P
        }
    }

    float4* __restrict__ o = out + (pix0 << 5) + lane;
    #pragma unroll
    for (int p = 0; p < P; p++) {
        __stcs(o + (p << 5), v[p]);    // streaming: write-once, evict-first
    }
}

extern "C" void kernel_launch(void* const* d_in, const int* in_sizes, int n_in,
                              void* d_out, int out_size)
{
    const float4* feat = (const float4*)d_in[0];   // graph_lstm_output fp32 [B,N,C]
    const int*    slic = (const int*)d_in[1];      // slic_output int32 [B,H,W,1]
    float4*       out  = (float4*)d_out;           // fp32 [B,H,W,C]

    const int threads = 256;                        // 8 warps -> 32 pixels/block
    const long long pixels_per_block = (threads / 32) * P;
    const unsigned blocks = (unsigned)((PIX + pixels_per_block - 1) / pixels_per_block); // 65,536

    convert2image_gather4<<<blocks, threads>>>(feat, slic, out);
}